// round 2
// baseline (speedup 1.0000x reference)
#include <cuda_runtime.h>
#include <cstdint>

// Problem constants
#define SQ      4096
#define HH      16
#define DD      64
#define HALFW   128
#define TQ      32                   // query rows per block
#define SPAN    (TQ + 2*HALFW)       // 288 key columns covered per block
#define KSTR    68                   // padded row stride (floats): 272B = 17*16B (odd) -> conflict-free LDS.128
#define PSTR    292                  // padded row stride for P (prob) buffer
#define THREADS 512

// Shared memory layout (in floats)
#define Q_OFF   0
#define K_OFF   (TQ*DD)                  // 2048
#define V_OFF   (K_OFF + SPAN*KSTR)      // 21632
#define P_OFF   (V_OFF + SPAN*KSTR)      // 41216
#define SMEM_FLOATS (P_OFF + TQ*PSTR)    // 50560
#define SMEM_BYTES  (SMEM_FLOATS * 4)    // 202240 bytes

__global__ __launch_bounds__(THREADS, 1)
void win_attn_kernel(const float* __restrict__ q,
                     const float* __restrict__ k,
                     const float* __restrict__ v,
                     float* __restrict__ out,   // [H, S, D]
                     float* __restrict__ attn)  // [H, S, S] (may be null)
{
    extern __shared__ float sm[];
    const int tile = blockIdx.x;           // 0..127
    const int h    = blockIdx.y;           // 0..15
    const int t0   = tile * TQ;
    const int span_start = t0 - HALFW;     // global col of span index 0 (multiple of 32, signed)
    const int tid  = threadIdx.x;

    // ---------------- Load Q tile (contiguous copy) ----------------
    {
        const float4* qg = reinterpret_cast<const float4*>(q) + (size_t)(h * SQ + t0) * (DD / 4);
        float4* Qs4 = reinterpret_cast<float4*>(sm + Q_OFF);
        if (tid < TQ * (DD / 4))
            Qs4[tid] = qg[tid];
    }

    // ---------------- Load K/V span (zero-fill outside [0,S)) ----------------
    {
        const float4* kg = reinterpret_cast<const float4*>(k) + (size_t)h * SQ * (DD / 4);
        const float4* vg = reinterpret_cast<const float4*>(v) + (size_t)h * SQ * (DD / 4);
        #pragma unroll 1
        for (int idx = tid; idx < SPAN * (DD / 4); idx += THREADS) {
            int c  = idx >> 4;           // span row
            int d4 = idx & 15;           // float4 within row
            int j  = span_start + c;     // global key index
            float4 kv = make_float4(0.f, 0.f, 0.f, 0.f);
            float4 vv = kv;
            if (j >= 0 && j < SQ) {
                kv = kg[j * 16 + d4];
                vv = vg[j * 16 + d4];
            }
            *reinterpret_cast<float4*>(sm + K_OFF + c * KSTR + d4 * 4) = kv;
            *reinterpret_cast<float4*>(sm + V_OFF + c * KSTR + d4 * 4) = vv;
        }
    }

    // ---------------- Zero P buffer ----------------
    {
        const float4 z4 = make_float4(0.f, 0.f, 0.f, 0.f);
        float4* Ps4 = reinterpret_cast<float4*>(sm + P_OFF);
        #pragma unroll 1
        for (int idx = tid; idx < (TQ * PSTR) / 4; idx += THREADS)
            Ps4[idx] = z4;
    }

    // ---------------- EARLY: stream the zero region of attn (no dependencies) ----
    // Band per global row gr covers float4 idx [s4, e4]; everything else is zero.
    // These STGs overlap with the K/V load latency and the whole compute phase.
    if (attn != nullptr) {
        float4* attn4 = reinterpret_cast<float4*>(attn);
        const float4 z4 = make_float4(0.f, 0.f, 0.f, 0.f);
        #pragma unroll 1
        for (int t = tid; t < TQ * (SQ / 4); t += THREADS) {
            int r  = t >> 10;                 // local row
            int i  = t & 1023;                // float4 index within row
            int gr = t0 + r;
            int s4 = (gr - HALFW) >> 2; if (s4 < 0) s4 = 0;
            int e4 = (gr + HALFW) >> 2; if (e4 > (SQ/4 - 1)) e4 = SQ/4 - 1;
            if (i < s4 || i > e4)
                attn4[(size_t)(h * SQ + gr) * (SQ / 4) + i] = z4;
        }
    }
    __syncthreads();

    // ---------------- Phase A: banded QK + softmax (warp per 2 rows) ----------------
    {
        const int w  = tid >> 5;
        const int l  = tid & 31;
        const int r0 = w * 2;            // this warp's first local row (16 warps x 2 rows)

        float s[2][9];
        #pragma unroll
        for (int rr = 0; rr < 2; rr++)
            #pragma unroll
            for (int u = 0; u < 9; u++) s[rr][u] = 0.f;

        int cidx[9];                     // clamped span indices (clamp keeps smem reads in-bounds; masked later)
        #pragma unroll
        for (int u = 0; u < 9; u++) {
            int c = r0 + l + 32 * u;
            cidx[u] = (c < SPAN) ? c : (SPAN - 1);
        }

        #pragma unroll 4
        for (int d4 = 0; d4 < 16; d4++) {
            float4 qv0 = *reinterpret_cast<const float4*>(sm + Q_OFF + (r0 + 0) * DD + d4 * 4);
            float4 qv1 = *reinterpret_cast<const float4*>(sm + Q_OFF + (r0 + 1) * DD + d4 * 4);
            #pragma unroll
            for (int u = 0; u < 9; u++) {
                float4 kv = *reinterpret_cast<const float4*>(sm + K_OFF + cidx[u] * KSTR + d4 * 4);
                s[0][u] += qv0.x * kv.x; s[0][u] += qv0.y * kv.y;
                s[0][u] += qv0.z * kv.z; s[0][u] += qv0.w * kv.w;
                s[1][u] += qv1.x * kv.x; s[1][u] += qv1.y * kv.y;
                s[1][u] += qv1.z * kv.z; s[1][u] += qv1.w * kv.w;
            }
        }

        #pragma unroll
        for (int rr = 0; rr < 2; rr++) {
            const int r = r0 + rr;
            float sv[9];
            float m = -3.0e38f;
            #pragma unroll
            for (int u = 0; u < 9; u++) {
                int c   = r0 + l + 32 * u;
                int off = c - r;                  // position within row window [0,256]
                int j   = span_start + c;
                bool valid = (off >= 0) & (off <= 2 * HALFW) & (j >= 0) & (j < SQ);
                sv[u] = valid ? s[rr][u] * 0.125f : -1.0e30f;
                m = fmaxf(m, sv[u]);
            }
            #pragma unroll
            for (int o = 16; o > 0; o >>= 1)
                m = fmaxf(m, __shfl_xor_sync(0xffffffffu, m, o));
            float sum = 0.f;
            #pragma unroll
            for (int u = 0; u < 9; u++) {
                sv[u] = __expf(sv[u] - m);        // invalid -> exp(-1e30) == 0
                sum += sv[u];
            }
            #pragma unroll
            for (int o = 16; o > 0; o >>= 1)
                sum += __shfl_xor_sync(0xffffffffu, sum, o);
            const float inv = __fdividef(1.f, sum);
            #pragma unroll
            for (int u = 0; u < 9; u++) {
                int c   = r0 + l + 32 * u;
                int off = c - r;
                int j   = span_start + c;
                if ((off >= 0) & (off <= 2 * HALFW) & (j >= 0) & (j < SQ))
                    sm[P_OFF + r * PSTR + c] = sv[u] * inv;
            }
        }
    }
    __syncthreads();

    // ---------------- Phase B: out = P * V  (thread computes 1 row x 4 cols) ----------------
    {
        const int rp = tid >> 4;         // 0..31 -> row
        const int cq = tid & 15;         // 0..15 -> cols 4cq..4cq+3
        float4 a = make_float4(0.f, 0.f, 0.f, 0.f);
        const float* pr = sm + P_OFF + rp * PSTR;
        #pragma unroll 4
        for (int c = 0; c < SPAN; c++) {
            float p = pr[c];
            float4 vv = *reinterpret_cast<const float4*>(sm + V_OFF + c * KSTR + cq * 4);
            a.x += p * vv.x; a.y += p * vv.y; a.z += p * vv.z; a.w += p * vv.w;
        }
        float4* out4 = reinterpret_cast<float4*>(out);
        out4[(size_t)(h * SQ + t0 + rp) * 16 + cq] = a;
    }

    // ---------------- Phase C: store the band region of attn from P ----------------
    // Per row: float4 idx i in [s4, e4]; c0 = 4*i - span_start is 16B-aligned into P,
    // and P is zeroed outside valid entries so boundary float4s pick up correct zeros.
    if (attn != nullptr) {
        float4* attn4 = reinterpret_cast<float4*>(attn);
        #pragma unroll 1
        for (int t = tid; t < TQ * 66; t += THREADS) {
            int r  = t / 66;
            int ii = t - r * 66;
            int gr = t0 + r;
            int s4 = (gr - HALFW) >> 2; if (s4 < 0) s4 = 0;
            int e4 = (gr + HALFW) >> 2; if (e4 > (SQ/4 - 1)) e4 = SQ/4 - 1;
            int i  = s4 + ii;
            if (i <= e4) {
                int c0 = 4 * i - span_start;       // >= 0, <= r+256, aligned
                float4 val = *reinterpret_cast<const float4*>(sm + P_OFF + r * PSTR + c0);
                attn4[(size_t)(h * SQ + gr) * (SQ / 4) + i] = val;
            }
        }
    }
}

extern "C" void kernel_launch(void* const* d_in, const int* in_sizes, int n_in,
                              void* d_out, int out_size) {
    const float* q = (const float*)d_in[0];
    const float* k = (const float*)d_in[1];
    const float* v = (const float*)d_in[2];
    float* out = (float*)d_out;

    const long long OUT_ELEMS = (long long)HH * SQ * DD;  // 4,194,304
    float* attn = ((long long)out_size > OUT_ELEMS) ? (out + OUT_ELEMS) : nullptr;

    cudaFuncSetAttribute(win_attn_kernel,
                         cudaFuncAttributeMaxDynamicSharedMemorySize, SMEM_BYTES);

    dim3 grid(SQ / TQ, HH);
    win_attn_kernel<<<grid, THREADS, SMEM_BYTES>>>(q, k, v, out, attn);
}

// round 3
// speedup vs baseline: 1.2295x; 1.2295x over previous
#include <cuda_runtime.h>
#include <cstdint>

// Problem constants
#define SQ      4096
#define HH      16
#define DD      64
#define HALFW   128
#define TQ      32                   // query rows per block
#define SPAN    (TQ + 2*HALFW)       // 288 key columns covered per block
#define KSTR    68                   // padded row stride (floats) for K/V
#define PSTR    292                  // padded row stride for P (prob) buffer
#define THREADS 512

// Shared memory layout (in floats)
#define Q_OFF   0
#define K_OFF   (TQ*DD)                  // 2048
#define V_OFF   (K_OFF + SPAN*KSTR)      // 21632
#define P_OFF   (V_OFF + SPAN*KSTR)      // 41216
#define RED_OFF K_OFF                    // reduction buffer reuses K region (4*32*64 = 8192 floats < 19584)
#define SMEM_FLOATS (P_OFF + TQ*PSTR)    // 50560
#define SMEM_BYTES  (SMEM_FLOATS * 4)    // 202240 bytes

__global__ __launch_bounds__(THREADS, 1)
void win_attn_kernel(const float* __restrict__ q,
                     const float* __restrict__ k,
                     const float* __restrict__ v,
                     float* __restrict__ out,   // [H, S, D]
                     float* __restrict__ attn)  // [H, S, S] (may be null)
{
    extern __shared__ float sm[];
    const int tile = blockIdx.x;           // 0..127
    const int h    = blockIdx.y;           // 0..15
    const int t0   = tile * TQ;
    const int span_start = t0 - HALFW;     // global col of span index 0 (multiple of 32, signed)
    const int tid  = threadIdx.x;

    // ---------------- Load Q tile ----------------
    {
        const float4* qg = reinterpret_cast<const float4*>(q) + (size_t)(h * SQ + t0) * (DD / 4);
        float4* Qs4 = reinterpret_cast<float4*>(sm + Q_OFF);
        if (tid < TQ * (DD / 4))
            Qs4[tid] = qg[tid];
    }

    // ---------------- Load K/V span (zero-fill outside [0,S)) ----------------
    {
        const float4* kg = reinterpret_cast<const float4*>(k) + (size_t)h * SQ * (DD / 4);
        const float4* vg = reinterpret_cast<const float4*>(v) + (size_t)h * SQ * (DD / 4);
        #pragma unroll 1
        for (int idx = tid; idx < SPAN * (DD / 4); idx += THREADS) {
            int c  = idx >> 4;           // span row
            int d4 = idx & 15;           // float4 within row
            int j  = span_start + c;     // global key index
            float4 kv = make_float4(0.f, 0.f, 0.f, 0.f);
            float4 vv = kv;
            if (j >= 0 && j < SQ) {
                kv = kg[j * 16 + d4];
                vv = vg[j * 16 + d4];
            }
            *reinterpret_cast<float4*>(sm + K_OFF + c * KSTR + d4 * 4) = kv;
            *reinterpret_cast<float4*>(sm + V_OFF + c * KSTR + d4 * 4) = vv;
        }
    }

    // ---------------- Zero P buffer ----------------
    {
        const float4 z4 = make_float4(0.f, 0.f, 0.f, 0.f);
        float4* Ps4 = reinterpret_cast<float4*>(sm + P_OFF);
        #pragma unroll 1
        for (int idx = tid; idx < (TQ * PSTR) / 4; idx += THREADS)
            Ps4[idx] = z4;
    }

    // ---------------- EARLY: stream the zero region of attn (no dependencies) ----
    if (attn != nullptr) {
        float4* attn4 = reinterpret_cast<float4*>(attn);
        const float4 z4 = make_float4(0.f, 0.f, 0.f, 0.f);
        #pragma unroll 1
        for (int t = tid; t < TQ * (SQ / 4); t += THREADS) {
            int r  = t >> 10;                 // local row
            int i  = t & 1023;                // float4 index within row
            int gr = t0 + r;
            int s4 = (gr - HALFW) >> 2; if (s4 < 0) s4 = 0;
            int e4 = (gr + HALFW) >> 2; if (e4 > (SQ/4 - 1)) e4 = SQ/4 - 1;
            if (i < s4 || i > e4)
                attn4[(size_t)(h * SQ + gr) * (SQ / 4) + i] = z4;
        }
    }
    __syncthreads();

    // ---------------- Phase A: banded QK + softmax (warp per 4 rows, warps 0..7) ----------------
    {
        const int w = tid >> 5;
        const int l = tid & 31;
        if (w < 8) {
            const int r0 = w * 4;

            float s[4][9];
            #pragma unroll
            for (int rr = 0; rr < 4; rr++)
                #pragma unroll
                for (int u = 0; u < 9; u++) s[rr][u] = 0.f;

            int cidx[9];                 // clamped span indices
            #pragma unroll
            for (int u = 0; u < 9; u++) {
                int c = r0 + l + 32 * u;
                cidx[u] = (c < SPAN) ? c : (SPAN - 1);
            }

            #pragma unroll 2
            for (int d4 = 0; d4 < 16; d4++) {
                float4 qv[4];
                #pragma unroll
                for (int rr = 0; rr < 4; rr++)
                    qv[rr] = *reinterpret_cast<const float4*>(sm + Q_OFF + (r0 + rr) * DD + d4 * 4);
                #pragma unroll
                for (int u = 0; u < 9; u++) {
                    float4 kv = *reinterpret_cast<const float4*>(sm + K_OFF + cidx[u] * KSTR + d4 * 4);
                    #pragma unroll
                    for (int rr = 0; rr < 4; rr++) {
                        s[rr][u] += qv[rr].x * kv.x;
                        s[rr][u] += qv[rr].y * kv.y;
                        s[rr][u] += qv[rr].z * kv.z;
                        s[rr][u] += qv[rr].w * kv.w;
                    }
                }
            }

            #pragma unroll
            for (int rr = 0; rr < 4; rr++) {
                const int r = r0 + rr;
                float sv[9];
                float m = -3.0e38f;
                #pragma unroll
                for (int u = 0; u < 9; u++) {
                    int c   = r0 + l + 32 * u;
                    int off = c - r;                  // position within row window [0,256]
                    int j   = span_start + c;
                    bool valid = (off >= 0) & (off <= 2 * HALFW) & (j >= 0) & (j < SQ);
                    sv[u] = valid ? s[rr][u] * 0.125f : -1.0e30f;
                    m = fmaxf(m, sv[u]);
                }
                #pragma unroll
                for (int o = 16; o > 0; o >>= 1)
                    m = fmaxf(m, __shfl_xor_sync(0xffffffffu, m, o));
                float sum = 0.f;
                #pragma unroll
                for (int u = 0; u < 9; u++) {
                    sv[u] = __expf(sv[u] - m);        // invalid -> exp(-1e30) == 0
                    sum += sv[u];
                }
                #pragma unroll
                for (int o = 16; o > 0; o >>= 1)
                    sum += __shfl_xor_sync(0xffffffffu, sum, o);
                const float inv = __fdividef(1.f, sum);
                #pragma unroll
                for (int u = 0; u < 9; u++) {
                    int c   = r0 + l + 32 * u;
                    int off = c - r;
                    int j   = span_start + c;
                    if ((off >= 0) & (off <= 2 * HALFW) & (j >= 0) & (j < SQ))
                        sm[P_OFF + r * PSTR + c] = sv[u] * inv;
                }
            }
        }
    }
    __syncthreads();

    // ---------------- Phase B: out = P * V, thread = 4 rows x 4 cols, 4-way span split ----
    {
        const int g  = tid >> 7;         // span group 0..3 -> cols [g*72, g*72+72)
        const int t  = tid & 127;
        const int rp = t >> 4;           // 0..7 -> rows 4rp..4rp+3
        const int cq = t & 15;           // 0..15 -> cols 4cq..4cq+3

        float4 a0 = make_float4(0.f,0.f,0.f,0.f);
        float4 a1 = a0, a2 = a0, a3 = a0;
        const float* p0 = sm + P_OFF + (rp * 4 + 0) * PSTR;
        const float* p1 = sm + P_OFF + (rp * 4 + 1) * PSTR;
        const float* p2 = sm + P_OFF + (rp * 4 + 2) * PSTR;
        const float* p3 = sm + P_OFF + (rp * 4 + 3) * PSTR;
        const int c0 = g * (SPAN / 4);
        #pragma unroll 4
        for (int cc = 0; cc < SPAN / 4; cc++) {
            const int c = c0 + cc;
            float4 vv = *reinterpret_cast<const float4*>(sm + V_OFF + c * KSTR + cq * 4);
            float q0 = p0[c], q1 = p1[c], q2 = p2[c], q3 = p3[c];
            a0.x += q0 * vv.x; a0.y += q0 * vv.y; a0.z += q0 * vv.z; a0.w += q0 * vv.w;
            a1.x += q1 * vv.x; a1.y += q1 * vv.y; a1.z += q1 * vv.z; a1.w += q1 * vv.w;
            a2.x += q2 * vv.x; a2.y += q2 * vv.y; a2.z += q2 * vv.z; a2.w += q2 * vv.w;
            a3.x += q3 * vv.x; a3.y += q3 * vv.y; a3.z += q3 * vv.z; a3.w += q3 * vv.w;
        }
        // partials -> smem (reuse K region; Phase A K reads are behind the sync above)
        float* red = sm + RED_OFF;       // layout [g][row][64]
        *reinterpret_cast<float4*>(red + ((g * TQ + rp * 4 + 0) * DD) + cq * 4) = a0;
        *reinterpret_cast<float4*>(red + ((g * TQ + rp * 4 + 1) * DD) + cq * 4) = a1;
        *reinterpret_cast<float4*>(red + ((g * TQ + rp * 4 + 2) * DD) + cq * 4) = a2;
        *reinterpret_cast<float4*>(red + ((g * TQ + rp * 4 + 3) * DD) + cq * 4) = a3;
    }
    __syncthreads();

    // ---------------- Reduce partials and store out ----------------
    {
        const int row = tid >> 4;        // 0..31
        const int c4  = tid & 15;        // 0..15
        const float* red = sm + RED_OFF;
        float4 r = make_float4(0.f,0.f,0.f,0.f);
        #pragma unroll
        for (int g = 0; g < 4; g++) {
            float4 pp = *reinterpret_cast<const float4*>(red + ((g * TQ + row) * DD) + c4 * 4);
            r.x += pp.x; r.y += pp.y; r.z += pp.z; r.w += pp.w;
        }
        float4* out4 = reinterpret_cast<float4*>(out);
        out4[(size_t)(h * SQ + t0 + row) * 16 + c4] = r;
    }

    // ---------------- Phase C: store the band region of attn from P ----------------
    if (attn != nullptr) {
        float4* attn4 = reinterpret_cast<float4*>(attn);
        #pragma unroll 1
        for (int t = tid; t < TQ * 66; t += THREADS) {
            int r  = t / 66;
            int ii = t - r * 66;
            int gr = t0 + r;
            int s4 = (gr - HALFW) >> 2; if (s4 < 0) s4 = 0;
            int e4 = (gr + HALFW) >> 2; if (e4 > (SQ/4 - 1)) e4 = SQ/4 - 1;
            int i  = s4 + ii;
            if (i <= e4) {
                int c0 = 4 * i - span_start;       // >= 0, aligned into P
                float4 val = *reinterpret_cast<const float4*>(sm + P_OFF + r * PSTR + c0);
                attn4[(size_t)(h * SQ + gr) * (SQ / 4) + i] = val;
            }
        }
    }
}

extern "C" void kernel_launch(void* const* d_in, const int* in_sizes, int n_in,
                              void* d_out, int out_size) {
    const float* q = (const float*)d_in[0];
    const float* k = (const float*)d_in[1];
    const float* v = (const float*)d_in[2];
    float* out = (float*)d_out;

    const long long OUT_ELEMS = (long long)HH * SQ * DD;  // 4,194,304
    float* attn = ((long long)out_size > OUT_ELEMS) ? (out + OUT_ELEMS) : nullptr;

    cudaFuncSetAttribute(win_attn_kernel,
                         cudaFuncAttributeMaxDynamicSharedMemorySize, SMEM_BYTES);

    dim3 grid(SQ / TQ, HH);
    win_attn_kernel<<<grid, THREADS, SMEM_BYTES>>>(q, k, v, out, attn);
}

// round 4
// speedup vs baseline: 1.6062x; 1.3064x over previous
#include <cuda_runtime.h>
#include <cstdint>

// Problem constants
#define SQ      4096
#define HH      16
#define DD      64
#define HALFW   128
#define TQ      32                    // query rows per block
#define SPAN    288                   // TQ + 2*HALFW key columns per block
#define KSTR    68                    // K/V smem row stride (floats): 272B = odd # of 16B -> conflict-free
#define PSTR    260                   // P diagonal-layout row stride (floats): 65x16B odd
#define THREADS 256

// Shared memory layout (floats). P (diagonal layout) first; Q overlays P rows 0..7
// (Q is dead before any P write thanks to the barrier after the QK phase).
#define P_OFF   0
#define Q_OFF   0
#define KV_OFF  (TQ*PSTR)                 // 8320
#define SMEM_FLOATS (KV_OFF + SPAN*KSTR) // 27904
#define SMEM_BYTES  (SMEM_FLOATS * 4)    // 111616 -> 2 CTAs/SM

__device__ __forceinline__ void cp16(uint32_t saddr, const void* gptr, int nbytes) {
    asm volatile("cp.async.cg.shared.global [%0], [%1], 16, %2;"
                 :: "r"(saddr), "l"(gptr), "r"(nbytes) : "memory");
}

__global__ __launch_bounds__(THREADS, 2)
void win_attn_kernel(const float* __restrict__ q,
                     const float* __restrict__ k,
                     const float* __restrict__ v,
                     float* __restrict__ out,   // [H, S, D]
                     float* __restrict__ attn)  // [H, S, S]
{
    extern __shared__ float sm[];
    const int tile = blockIdx.x;           // 0..127
    const int h    = blockIdx.y;           // 0..15
    const int t0   = tile * TQ;
    const int span_start = t0 - HALFW;     // multiple of 4 (signed)
    const int tid  = threadIdx.x;
    const int w    = tid >> 5;
    const int l    = tid & 31;
    const uint32_t smb = (uint32_t)__cvta_generic_to_shared(sm);

    // ---------------- Issue Q + K cp.async (overlap with zero stores) ----------------
    {
        const float4* qg = reinterpret_cast<const float4*>(q) + (size_t)(h * SQ + t0) * 16;
        #pragma unroll
        for (int i = tid; i < TQ * 16; i += THREADS)
            cp16(smb + (Q_OFF) * 4 + i * 16, qg + i, 16);

        const float4* kg = reinterpret_cast<const float4*>(k) + (size_t)h * SQ * 16;
        #pragma unroll 2
        for (int i = tid; i < SPAN * 16; i += THREADS) {
            int c  = i >> 4;
            int d4 = i & 15;
            int j  = span_start + c;
            int jc = (j < 0) ? 0 : ((j >= SQ) ? 0 : j);
            int n  = (j >= 0 && j < SQ) ? 16 : 0;     // n=0 -> zero-fill
            cp16(smb + (KV_OFF + c * KSTR + d4 * 4) * 4, kg + (size_t)jc * 16 + d4, n);
        }
        asm volatile("cp.async.commit_group;" ::: "memory");
    }

    // ---------------- EARLY: zero region of attn (warp per 4 rows, contiguous) ------
    if (attn != nullptr) {
        float4* attn4 = reinterpret_cast<float4*>(attn);
        const float4 z4 = make_float4(0.f, 0.f, 0.f, 0.f);
        #pragma unroll
        for (int rr = 0; rr < 4; rr++) {
            int r  = w * 4 + rr;
            int gr = t0 + r;
            int s4 = (gr - HALFW) >> 2; if (s4 < 0) s4 = 0;
            int e4 = (gr + HALFW) >> 2; if (e4 > 1023) e4 = 1023;
            float4* rowp = attn4 + (size_t)(h * SQ + gr) * 1024;
            #pragma unroll 1
            for (int i = l; i < s4; i += 32) rowp[i] = z4;
            #pragma unroll 1
            for (int i = e4 + 1 + l; i < 1024; i += 32) rowp[i] = z4;
        }
    }

    asm volatile("cp.async.wait_all;" ::: "memory");
    __syncthreads();

    // ---------------- Phase A1: banded QK scores into registers (warp per 4 rows) ---
    const int r0 = w * 4;
    float s[4][9];
    #pragma unroll
    for (int rr = 0; rr < 4; rr++)
        #pragma unroll
        for (int u = 0; u < 9; u++) s[rr][u] = 0.f;
    {
        int cidx[9];
        #pragma unroll
        for (int u = 0; u < 9; u++) {
            int c = r0 + l + 32 * u;
            cidx[u] = (c < SPAN) ? c : (SPAN - 1);
        }
        #pragma unroll 2
        for (int d4 = 0; d4 < 16; d4++) {
            float4 qv[4];
            #pragma unroll
            for (int rr = 0; rr < 4; rr++)
                qv[rr] = *reinterpret_cast<const float4*>(sm + Q_OFF + (r0 + rr) * DD + d4 * 4);
            #pragma unroll
            for (int u = 0; u < 9; u++) {
                float4 kv = *reinterpret_cast<const float4*>(sm + KV_OFF + cidx[u] * KSTR + d4 * 4);
                #pragma unroll
                for (int rr = 0; rr < 4; rr++) {
                    s[rr][u] += qv[rr].x * kv.x;
                    s[rr][u] += qv[rr].y * kv.y;
                    s[rr][u] += qv[rr].z * kv.z;
                    s[rr][u] += qv[rr].w * kv.w;
                }
            }
        }
    }
    __syncthreads();   // all Q/K smem reads complete

    // ---------------- Issue V cp.async (overwrites K region; hides under softmax) ---
    {
        const float4* vg = reinterpret_cast<const float4*>(v) + (size_t)h * SQ * 16;
        #pragma unroll 2
        for (int i = tid; i < SPAN * 16; i += THREADS) {
            int c  = i >> 4;
            int d4 = i & 15;
            int j  = span_start + c;
            int jc = (j < 0) ? 0 : ((j >= SQ) ? 0 : j);
            int n  = (j >= 0 && j < SQ) ? 16 : 0;
            cp16(smb + (KV_OFF + c * KSTR + d4 * 4) * 4, vg + (size_t)jc * 16 + d4, n);
        }
        asm volatile("cp.async.commit_group;" ::: "memory");
    }

    // ---------------- Phase A2: softmax + write P in diagonal layout -----------------
    // P[r][o] holds prob for span col c = r0 + o (r0 = r & ~3). Masked entries are
    // exactly 0 (expf(-1e30) == 0), so no separate zero pass is needed.
    #pragma unroll
    for (int rr = 0; rr < 4; rr++) {
        const int r = r0 + rr;
        float sv[9];
        float m = -3.0e38f;
        #pragma unroll
        for (int u = 0; u < 9; u++) {
            int o   = l + 32 * u;
            int off = o - rr;                 // position within row window [0,256]
            int j   = span_start + r0 + o;
            bool valid = (off >= 0) & (off <= 2 * HALFW) & (j >= 0) & (j < SQ);
            sv[u] = valid ? s[rr][u] * 0.125f : -1.0e30f;
            m = fmaxf(m, sv[u]);
        }
        #pragma unroll
        for (int o = 16; o > 0; o >>= 1)
            m = fmaxf(m, __shfl_xor_sync(0xffffffffu, m, o));
        float sum = 0.f;
        #pragma unroll
        for (int u = 0; u < 9; u++) {
            sv[u] = __expf(sv[u] - m);
            sum += sv[u];
        }
        #pragma unroll
        for (int o = 16; o > 0; o >>= 1)
            sum += __shfl_xor_sync(0xffffffffu, sum, o);
        const float inv = __fdividef(1.f, sum);
        #pragma unroll
        for (int u = 0; u < 9; u++) {
            int o = l + 32 * u;
            if (o < PSTR)
                sm[P_OFF + r * PSTR + o] = sv[u] * inv;
        }
    }

    asm volatile("cp.async.wait_all;" ::: "memory");
    __syncthreads();   // P complete block-wide, V landed

    // ---------------- Phase C: band stores of attn (issued first so STGs drain under
    //                  Phase B's FMA work); warp per 4 rows, contiguous ---------------
    if (attn != nullptr) {
        float4* attn4 = reinterpret_cast<float4*>(attn);
        #pragma unroll
        for (int rr = 0; rr < 4; rr++) {
            int r  = r0 + rr;
            int gr = t0 + r;
            int s4 = (gr - HALFW) >> 2; if (s4 < 0) s4 = 0;
            int e4 = (gr + HALFW) >> 2; if (e4 > 1023) e4 = 1023;
            float4* rowp = attn4 + (size_t)(h * SQ + gr) * 1024;
            const float* pr = sm + P_OFF + r * PSTR - r0;   // index by c0 = 4i - span_start
            #pragma unroll 1
            for (int i = s4 + l; i <= e4; i += 32) {
                int c0 = 4 * i - span_start;                // c0 - r0 in [0, 259], 16B-aligned
                rowp[i] = *reinterpret_cast<const float4*>(pr + c0);
            }
        }
    }

    // ---------------- Phase B: out = P * V (thread = 2 rows x 4 cols, full span) -----
    {
        const int rp = tid >> 4;          // 0..15
        const int cq = tid & 15;          // 0..15
        const int ra = 2 * rp, rb = ra + 1;
        const int rbase = ra & ~3;        // shared P-offset base for both rows
        float4 a0 = make_float4(0.f, 0.f, 0.f, 0.f);
        float4 a1 = a0;
        const float* p0 = sm + P_OFF + ra * PSTR;
        const float* p1 = sm + P_OFF + rb * PSTR;
        const float* vb = sm + KV_OFF + rbase * KSTR + cq * 4;
        #pragma unroll 4
        for (int o = 0; o < PSTR; o++) {
            float4 vv = *reinterpret_cast<const float4*>(vb + o * KSTR);
            float x0 = p0[o];
            float x1 = p1[o];
            a0.x += x0 * vv.x; a0.y += x0 * vv.y; a0.z += x0 * vv.z; a0.w += x0 * vv.w;
            a1.x += x1 * vv.x; a1.y += x1 * vv.y; a1.z += x1 * vv.z; a1.w += x1 * vv.w;
        }
        float4* out4 = reinterpret_cast<float4*>(out);
        out4[(size_t)(h * SQ + t0 + ra) * 16 + cq] = a0;
        out4[(size_t)(h * SQ + t0 + rb) * 16 + cq] = a1;
    }
}

extern "C" void kernel_launch(void* const* d_in, const int* in_sizes, int n_in,
                              void* d_out, int out_size) {
    const float* q = (const float*)d_in[0];
    const float* k = (const float*)d_in[1];
    const float* v = (const float*)d_in[2];
    float* out = (float*)d_out;

    const long long OUT_ELEMS = (long long)HH * SQ * DD;  // 4,194,304
    float* attn = ((long long)out_size > OUT_ELEMS) ? (out + OUT_ELEMS) : nullptr;

    cudaFuncSetAttribute(win_attn_kernel,
                         cudaFuncAttributeMaxDynamicSharedMemorySize, SMEM_BYTES);

    dim3 grid(SQ / TQ, HH);
    win_attn_kernel<<<grid, THREADS, SMEM_BYTES>>>(q, k, v, out, attn);
}